// round 9
// baseline (speedup 1.0000x reference)
#include <cuda_runtime.h>
#include <cstdint>

// Shapes fixed by problem: N=1024 nodes, D=256 feat, H=256 hidden.
#define NN 1024
#define DD 256
#define HH 256
#define NBLK 128          // <= 148 SMs, 1 CTA/SM -> all co-resident -> device barrier safe
#define NTHR 512          // 16 warps/block

// Scratch (__device__ globals: allocation-free rule)
__device__ float g_p[DD];     // w1[:D] @ w2
__device__ float g_q[DD];     // w1[D:] @ w2
__device__ float g_c;         // b1.w2 + b2
__device__ float g_eu[NN];    // exp(-(u_i + c))
__device__ float g_ev[NN];    // exp(-v_i)
__device__ float g_s[NN];     // eu_i * ev_i

// Distributed epoch barrier: one flag per CTA, values monotonically increase
// across launches (no reset ever needed -> graph-replay safe).
__device__ unsigned g_flags[NBLK];   // zero-init at module load
__device__ unsigned g_base = 0;      // epoch base; block 0 advances by 2 per launch

__device__ __forceinline__ float warp_reduce(float v) {
#pragma unroll
    for (int o = 16; o > 0; o >>= 1) v += __shfl_xor_sync(0xffffffffu, v, o);
    return v;
}

__device__ __forceinline__ float frcp(float x) {
    float y;
    asm("rcp.approx.f32 %0, %1;" : "=f"(y) : "f"(x));
    return y;
}

__device__ __forceinline__ void st_release(unsigned* p, unsigned v) {
    asm volatile("st.global.release.gpu.u32 [%0], %1;" :: "l"(p), "r"(v) : "memory");
}
__device__ __forceinline__ void st_relaxed(unsigned* p, unsigned v) {
    asm volatile("st.global.relaxed.gpu.u32 [%0], %1;" :: "l"(p), "r"(v) : "memory");
}
__device__ __forceinline__ unsigned ld_relaxed(const unsigned* p) {
    unsigned v;
    asm volatile("ld.global.relaxed.gpu.u32 %0, [%1];" : "=r"(v) : "l"(p) : "memory");
    return v;
}
__device__ __forceinline__ uint4 ld_acquire_v4(const unsigned* p) {
    uint4 v;
    asm volatile("ld.acquire.gpu.global.v4.u32 {%0,%1,%2,%3}, [%4];"
                 : "=r"(v.x), "=r"(v.y), "=r"(v.z), "=r"(v.w) : "l"(p) : "memory");
    return v;
}

// Distributed-flag grid barrier. `target` is this crossing's epoch value.
// Critical path: last st.release visible (~L2 lat) + poll detect. No central
// atomic round-trips. All NBLK CTAs co-resident -> spin is deadlock-free.
__device__ __forceinline__ void grid_barrier(unsigned target) {
    __syncthreads();
    if (threadIdx.x == 0) st_release(&g_flags[blockIdx.x], target);
    if (threadIdx.x < 32) {
        const unsigned lane = threadIdx.x;
        bool ok;
        do {
            uint4 f = ld_acquire_v4(&g_flags[lane * 4]);  // 32 lanes x 4 flags = 128
            ok = (f.x >= target) & (f.y >= target) & (f.z >= target) & (f.w >= target);
        } while (!__all_sync(0xffffffffu, ok));
    }
    __syncthreads();
}

__global__ void __launch_bounds__(NTHR, 1)
fused_decoder(const float* __restrict__ z,  const float* __restrict__ w1,
              const float* __restrict__ b1, const float* __restrict__ w2,
              const float* __restrict__ b2, float* __restrict__ out) {
    const int lane  = threadIdx.x & 31;
    const int wid   = threadIdx.x >> 5;                       // 0..15
    const int gwarp = blockIdx.x * (NTHR / 32) + wid;         // 0..2047

    // Epoch base for this launch (written by block 0 at end of previous launch;
    // kernel-boundary ordering makes it visible here).
    const unsigned base = ld_relaxed(&g_base);

    // ---- Phase A loads FIRST (they gate the dependency chain) ----
    const float4* w2v = reinterpret_cast<const float4*>(w2);
    float4 a0, a1, r0, r1;
    const bool doA = (gwarp <= 2 * DD);
    if (doA) {
        const float4* row = (gwarp < 2 * DD)
            ? reinterpret_cast<const float4*>(w1 + (size_t)gwarp * HH)
            : reinterpret_cast<const float4*>(b1);
        r0 = row[lane];
        r1 = row[lane + 32];
        a0 = w2v[lane];
        a1 = w2v[lane + 32];
    }

    // ---- Prefetch phase-B inputs (z row): latency overlaps phase A + barrier ----
    float4 z0 = make_float4(0.f, 0.f, 0.f, 0.f);
    float4 z1 = z0;
    if (gwarp < NN) {
        const float4* zrow = reinterpret_cast<const float4*>(z + (size_t)gwarp * DD);
        z0 = zrow[lane];
        z1 = zrow[lane + 32];
    }

    // ---- Phase A compute: p = w1_top@w2, q = w1_bot@w2, c = b1.w2 + b2 ----
    if (doA) {
        float acc = r0.x * a0.x;
        acc = fmaf(r0.y, a0.y, acc);
        acc = fmaf(r0.z, a0.z, acc);
        acc = fmaf(r0.w, a0.w, acc);
        acc = fmaf(r1.x, a1.x, acc);
        acc = fmaf(r1.y, a1.y, acc);
        acc = fmaf(r1.z, a1.z, acc);
        acc = fmaf(r1.w, a1.w, acc);
        acc = warp_reduce(acc);
        if (lane == 0) {
            if (gwarp < DD)           g_p[gwarp] = acc;
            else if (gwarp < 2 * DD)  g_q[gwarp - DD] = acc;
            else                      g_c = acc + b2[0];
        }
    }

    grid_barrier(base + 1u);

    // ---- Phase B: eu_i = exp(-(z_i.p + c)), ev_i = exp(-(z_i.q)), s_i = eu_i*ev_i ----
    if (gwarp < NN) {
        const float4* pv = reinterpret_cast<const float4*>(g_p);
        const float4* qv = reinterpret_cast<const float4*>(g_q);
        float4 p0 = pv[lane], p1 = pv[lane + 32];
        float4 q0 = qv[lane], q1 = qv[lane + 32];
        float su = z0.x * p0.x;
        su = fmaf(z0.y, p0.y, su);
        su = fmaf(z0.z, p0.z, su);
        su = fmaf(z0.w, p0.w, su);
        su = fmaf(z1.x, p1.x, su);
        su = fmaf(z1.y, p1.y, su);
        su = fmaf(z1.z, p1.z, su);
        su = fmaf(z1.w, p1.w, su);
        float sv = z0.x * q0.x;
        sv = fmaf(z0.y, q0.y, sv);
        sv = fmaf(z0.z, q0.z, sv);
        sv = fmaf(z0.w, q0.w, sv);
        sv = fmaf(z1.x, q1.x, sv);
        sv = fmaf(z1.y, q1.y, sv);
        sv = fmaf(z1.z, q1.z, sv);
        sv = fmaf(z1.w, q1.w, sv);
        su = warp_reduce(su);
        sv = warp_reduce(sv);
        if (lane == 0) {
            float eu = __expf(-(su + g_c));
            float ev = __expf(-sv);
            g_eu[gwarp] = eu;
            g_ev[gwarp] = ev;
            g_s[gwarp]  = eu * ev;
        }
    }

    grid_barrier(base + 2u);

    // ---- Phase C: adj[i,j] = (0.5*B + 0.5) / (B + s_i*s_j),
    //      B = 1 + eu_i*ev_j + eu_j*ev_i  (5 FMA-class + 1 MUFU per element) ----
    const int colg    = threadIdx.x & 255;      // float4 column group 0..255
    const int row_sub = threadIdx.x >> 8;       // 0..1
    const float4 euj = reinterpret_cast<const float4*>(g_eu)[colg];
    const float4 evj = reinterpret_cast<const float4*>(g_ev)[colg];
    const float4 sj  = reinterpret_cast<const float4*>(g_s)[colg];
#pragma unroll
    for (int rr = 0; rr < 4; rr++) {
        const int i = blockIdx.x * 8 + rr * 2 + row_sub;
        const float eui = g_eu[i];
        const float evi = g_ev[i];
        const float si  = g_s[i];
        float4 o;
        {
            float B = fmaf(euj.x, evi, fmaf(eui, evj.x, 1.f));
            o.x = fmaf(0.5f, B, 0.5f) * frcp(fmaf(si, sj.x, B));
        }
        {
            float B = fmaf(euj.y, evi, fmaf(eui, evj.y, 1.f));
            o.y = fmaf(0.5f, B, 0.5f) * frcp(fmaf(si, sj.y, B));
        }
        {
            float B = fmaf(euj.z, evi, fmaf(eui, evj.z, 1.f));
            o.z = fmaf(0.5f, B, 0.5f) * frcp(fmaf(si, sj.z, B));
        }
        {
            float B = fmaf(euj.w, evi, fmaf(eui, evj.w, 1.f));
            o.w = fmaf(0.5f, B, 0.5f) * frcp(fmaf(si, sj.w, B));
        }
        reinterpret_cast<float4*>(out)[(size_t)i * (NN / 4) + colg] = o;
    }

    // Advance epoch base for the next launch. Safe: every CTA captured `base`
    // before crossing 1, and crossing 2 completion implies that.
    if (blockIdx.x == 0 && threadIdx.x == 0) st_relaxed(&g_base, base + 2u);
}

extern "C" void kernel_launch(void* const* d_in, const int* in_sizes, int n_in,
                              void* d_out, int out_size) {
    const float* z  = (const float*)d_in[0];  // [N, D]
    const float* w1 = (const float*)d_in[1];  // [2D, H]
    const float* b1 = (const float*)d_in[2];  // [H]
    const float* w2 = (const float*)d_in[3];  // [H]
    const float* b2 = (const float*)d_in[4];  // [1]
    float* out = (float*)d_out;               // [N, N]

    fused_decoder<<<NBLK, NTHR>>>(z, w1, b1, w2, b2, out);
}

// round 10
// speedup vs baseline: 2.1463x; 2.1463x over previous
#include <cuda_runtime.h>
#include <cstdint>

// Shapes fixed by problem: N=1024 nodes, D=256 feat, H=256 hidden.
#define NN 1024
#define DD 256
#define HH 256
#define NBLK 128          // <= 148 SMs, 1 CTA/SM -> all co-resident -> device barrier safe
#define NTHR 512          // 16 warps/block

// Scratch (__device__ globals: allocation-free rule)
__device__ float g_p[DD];     // w1[:D] @ w2
__device__ float g_q[DD];     // w1[D:] @ w2
__device__ float g_c;         // b1.w2 + b2
__device__ float g_eu[NN];    // exp(-(u_i + c))
__device__ float g_ev[NN];    // exp(-v_i)
__device__ float g_s[NN];     // eu_i * ev_i

// Monotonic arrival counter (never reset -> graph-replay safe) + epoch base.
__device__ unsigned g_ctr  = 0;
__device__ unsigned g_base = 0;   // advanced by 2*NBLK per launch by block 0

__device__ __forceinline__ float warp_reduce(float v) {
#pragma unroll
    for (int o = 16; o > 0; o >>= 1) v += __shfl_xor_sync(0xffffffffu, v, o);
    return v;
}

__device__ __forceinline__ float frcp(float x) {
    float y;
    asm("rcp.approx.f32 %0, %1;" : "=f"(y) : "f"(x));
    return y;
}

__device__ __forceinline__ unsigned ld_relaxed(const unsigned* p) {
    unsigned v;
    asm volatile("ld.relaxed.gpu.global.u32 %0, [%1];" : "=r"(v) : "l"(p) : "memory");
    return v;
}
__device__ __forceinline__ void st_relaxed(unsigned* p, unsigned v) {
    asm volatile("st.relaxed.gpu.global.u32 [%0], %1;" :: "l"(p), "r"(v) : "memory");
}
__device__ __forceinline__ void red_add_release(unsigned* p, unsigned a) {
    asm volatile("red.release.gpu.global.add.u32 [%0], %1;" :: "l"(p), "r"(a) : "memory");
}
__device__ __forceinline__ void fence_acq_rel() {
    asm volatile("fence.acq_rel.gpu;" ::: "memory");
}

// Grid barrier on a monotonic counter. Arrival is fire-and-forget (red.release,
// no return round-trip); pollers watch the counter itself reach `target` with
// 4 pipelined relaxed loads (detection granularity ~RT/4), then an acq_rel
// fence provides acquire ordering. All NBLK CTAs co-resident -> deadlock-free.
__device__ __forceinline__ void grid_barrier(unsigned target) {
    __syncthreads();
    if (threadIdx.x == 0) {
        red_add_release(&g_ctr, 1u);          // release this CTA's prior writes
        unsigned v;
        do {
            unsigned a = ld_relaxed(&g_ctr);
            unsigned b = ld_relaxed(&g_ctr);
            unsigned c = ld_relaxed(&g_ctr);
            unsigned d = ld_relaxed(&g_ctr);
            v = a > b ? a : b;
            unsigned w = c > d ? c : d;
            v = v > w ? v : w;
        } while ((int)(v - target) < 0);      // wrap-safe monotonic compare
        fence_acq_rel();                      // acquire: observe peers' data writes
    }
    __syncthreads();
}

__global__ void __launch_bounds__(NTHR, 1)
fused_decoder(const float* __restrict__ z,  const float* __restrict__ w1,
              const float* __restrict__ b1, const float* __restrict__ w2,
              const float* __restrict__ b2, float* __restrict__ out) {
    const int lane  = threadIdx.x & 31;
    const int wid   = threadIdx.x >> 5;                       // 0..15
    const int gwarp = blockIdx.x * (NTHR / 32) + wid;         // 0..2047

    // Epoch base for this launch. Every CTA reads it at entry (i.e., before its
    // own first arrival); block 0 only rewrites it after barrier 2 completes,
    // which causally follows all entries. Kernel-boundary ordering publishes
    // it to the next launch.
    const unsigned base = ld_relaxed(&g_base);

    // ---- Phase A loads FIRST (they gate the dependency chain) ----
    const float4* w2v = reinterpret_cast<const float4*>(w2);
    float4 a0, a1, r0, r1;
    const bool doA = (gwarp <= 2 * DD);
    if (doA) {
        const float4* row = (gwarp < 2 * DD)
            ? reinterpret_cast<const float4*>(w1 + (size_t)gwarp * HH)
            : reinterpret_cast<const float4*>(b1);
        r0 = row[lane];
        r1 = row[lane + 32];
        a0 = w2v[lane];
        a1 = w2v[lane + 32];
    }

    // ---- Prefetch phase-B inputs (z row): latency overlaps phase A + barrier ----
    float4 z0 = make_float4(0.f, 0.f, 0.f, 0.f);
    float4 z1 = z0;
    if (gwarp < NN) {
        const float4* zrow = reinterpret_cast<const float4*>(z + (size_t)gwarp * DD);
        z0 = zrow[lane];
        z1 = zrow[lane + 32];
    }

    // ---- Phase A compute: p = w1_top@w2, q = w1_bot@w2, c = b1.w2 + b2 ----
    if (doA) {
        float acc = r0.x * a0.x;
        acc = fmaf(r0.y, a0.y, acc);
        acc = fmaf(r0.z, a0.z, acc);
        acc = fmaf(r0.w, a0.w, acc);
        acc = fmaf(r1.x, a1.x, acc);
        acc = fmaf(r1.y, a1.y, acc);
        acc = fmaf(r1.z, a1.z, acc);
        acc = fmaf(r1.w, a1.w, acc);
        acc = warp_reduce(acc);
        if (lane == 0) {
            if (gwarp < DD)           g_p[gwarp] = acc;
            else if (gwarp < 2 * DD)  g_q[gwarp - DD] = acc;
            else                      g_c = acc + b2[0];
        }
    }

    grid_barrier(base + NBLK);

    // ---- Phase B: eu_i = exp(-(z_i.p + c)), ev_i = exp(-(z_i.q)), s_i = eu_i*ev_i ----
    if (gwarp < NN) {
        const float4* pv = reinterpret_cast<const float4*>(g_p);
        const float4* qv = reinterpret_cast<const float4*>(g_q);
        float4 p0 = pv[lane], p1 = pv[lane + 32];
        float4 q0 = qv[lane], q1 = qv[lane + 32];
        float su = z0.x * p0.x;
        su = fmaf(z0.y, p0.y, su);
        su = fmaf(z0.z, p0.z, su);
        su = fmaf(z0.w, p0.w, su);
        su = fmaf(z1.x, p1.x, su);
        su = fmaf(z1.y, p1.y, su);
        su = fmaf(z1.z, p1.z, su);
        su = fmaf(z1.w, p1.w, su);
        float sv = z0.x * q0.x;
        sv = fmaf(z0.y, q0.y, sv);
        sv = fmaf(z0.z, q0.z, sv);
        sv = fmaf(z0.w, q0.w, sv);
        sv = fmaf(z1.x, q1.x, sv);
        sv = fmaf(z1.y, q1.y, sv);
        sv = fmaf(z1.z, q1.z, sv);
        sv = fmaf(z1.w, q1.w, sv);
        su = warp_reduce(su);
        sv = warp_reduce(sv);
        if (lane == 0) {
            float eu = __expf(-(su + g_c));
            float ev = __expf(-sv);
            g_eu[gwarp] = eu;
            g_ev[gwarp] = ev;
            g_s[gwarp]  = eu * ev;
        }
    }

    grid_barrier(base + 2u * NBLK);

    // ---- Phase C: adj[i,j] = (0.5*B + 0.5) / (B + s_i*s_j),
    //      B = 1 + eu_i*ev_j + eu_j*ev_i  (5 FMA-class + 1 MUFU per element) ----
    const int colg    = threadIdx.x & 255;      // float4 column group 0..255
    const int row_sub = threadIdx.x >> 8;       // 0..1
    const float4 euj = reinterpret_cast<const float4*>(g_eu)[colg];
    const float4 evj = reinterpret_cast<const float4*>(g_ev)[colg];
    const float4 sj  = reinterpret_cast<const float4*>(g_s)[colg];
#pragma unroll
    for (int rr = 0; rr < 4; rr++) {
        const int i = blockIdx.x * 8 + rr * 2 + row_sub;
        const float eui = g_eu[i];
        const float evi = g_ev[i];
        const float si  = g_s[i];
        float4 o;
        {
            float B = fmaf(euj.x, evi, fmaf(eui, evj.x, 1.f));
            o.x = fmaf(0.5f, B, 0.5f) * frcp(fmaf(si, sj.x, B));
        }
        {
            float B = fmaf(euj.y, evi, fmaf(eui, evj.y, 1.f));
            o.y = fmaf(0.5f, B, 0.5f) * frcp(fmaf(si, sj.y, B));
        }
        {
            float B = fmaf(euj.z, evi, fmaf(eui, evj.z, 1.f));
            o.z = fmaf(0.5f, B, 0.5f) * frcp(fmaf(si, sj.z, B));
        }
        {
            float B = fmaf(euj.w, evi, fmaf(eui, evj.w, 1.f));
            o.w = fmaf(0.5f, B, 0.5f) * frcp(fmaf(si, sj.w, B));
        }
        reinterpret_cast<float4*>(out)[(size_t)i * (NN / 4) + colg] = o;
    }

    // Advance epoch base for the next launch (after barrier 2 -> causally after
    // every CTA's entry read of g_base in this launch).
    if (blockIdx.x == 0 && threadIdx.x == 0) st_relaxed(&g_base, base + 2u * NBLK);
}

extern "C" void kernel_launch(void* const* d_in, const int* in_sizes, int n_in,
                              void* d_out, int out_size) {
    const float* z  = (const float*)d_in[0];  // [N, D]
    const float* w1 = (const float*)d_in[1];  // [2D, H]
    const float* b1 = (const float*)d_in[2];  // [H]
    const float* w2 = (const float*)d_in[3];  // [H]
    const float* b2 = (const float*)d_in[4];  // [1]
    float* out = (float*)d_out;               // [N, N]

    fused_decoder<<<NBLK, NTHR>>>(z, w1, b1, w2, b2, out);
}